// round 12
// baseline (speedup 1.0000x reference)
#include <cuda_runtime.h>
#include <stdint.h>

#define MAXPIX 4194304
#define QBINS (1 << 20)
#define SLICES 64
#define SLICEB (QBINS / SLICES)   // 16384

// ---------------- device scratch (zero-initialized at load) ----------------
__device__ double             g_acc[9];
__device__ unsigned long long g_cnt;
__device__ unsigned           g_hq[3][QBINS];    // phi, C0, C1 linear histograms (12 MB)
__device__ unsigned           g_bsum[3][SLICES];
__device__ unsigned           g_pack[MAXPIX];    // packed byte triples
__device__ float              g_E[6];
__device__ float              g_A[6];
__device__ float              g_G[9];
__device__ unsigned           g_tick[2];

// ---------------- constants ----------------
#define PHI_LO   (-3.14159274f)
#define PHI_SCALE ((float)QBINS / 6.28318530f)
#define PHI_INV  (6.28318530f / (float)QBINS)
#define C_LO     (-32.0f)
#define C_SCALE  ((float)QBINS / 64.0f)
#define C_INV    (64.0f / (float)QBINS)

// ---------------- helpers ----------------
#define BUILD_LUT(lut) \
  do { \
    if (threadIdx.x < 256) \
      lut[threadIdx.x] = -__logf((float)(threadIdx.x + 1) * (1.0f / 240.0f)); \
    __syncthreads(); \
  } while (0)

__device__ __forceinline__ int qbin(float x, float lo, float scale){
  int b = (int)((x - lo) * scale);
  return min(max(b, 0), QBINS - 1);
}

// blockDim-generic exclusive scan (blockDim multiple of 32, <=1024)
__device__ unsigned blk_exscan(unsigned v){
  __shared__ unsigned ws[32];
  int lane = threadIdx.x & 31, w = threadIdx.x >> 5;
  int nw = blockDim.x >> 5;
  unsigned x = v;
  #pragma unroll
  for (int o = 1; o < 32; o <<= 1){
    unsigned y = __shfl_up_sync(0xffffffffu, x, o);
    if (lane >= o) x += y;
  }
  if (lane == 31) ws[w] = x;
  __syncthreads();
  if (threadIdx.x < 32){
    unsigned t = (lane < nw) ? ws[lane] : 0u;
    #pragma unroll
    for (int o = 1; o < 32; o <<= 1){
      unsigned y = __shfl_up_sync(0xffffffffu, t, o);
      if (lane >= o) t += y;
    }
    ws[lane] = t;
  }
  __syncthreads();
  unsigned base = (w == 0) ? 0u : ws[w - 1];
  unsigned res = base + x - v;
  __syncthreads();
  return res;
}

// resolve rank -> bin over a QBINS histogram using slice sums (block-collective)
__device__ unsigned resolve_bin(const unsigned* __restrict__ hist,
                                const unsigned* __restrict__ bsum, unsigned rank){
  __shared__ unsigned s_slice, s_rib, s_bin;
  if (threadIdx.x == 0){
    unsigned cum = 0;
    s_slice = SLICES - 1; s_rib = 0;
    for (int s = 0; s < SLICES; s++){
      unsigned v = bsum[s];
      if (rank < cum + v){ s_slice = (unsigned)s; s_rib = rank - cum; break; }
      cum += v;
    }
  }
  __syncthreads();
  unsigned slice = s_slice, r = s_rib;
  const uint4* H = (const uint4*)(hist + slice * SLICEB);
  int per = (SLICEB / blockDim.x) / 4;
  unsigned base4 = threadIdx.x * per;
  unsigned s = 0;
  for (int b = 0; b < per; b++){
    uint4 u = H[base4 + b];
    s += u.x + u.y + u.z + u.w;
  }
  unsigned cum = blk_exscan(s);
  if (r >= cum && r < cum + s){
    unsigned c2 = cum;
    for (int b = 0; b < per; b++){
      uint4 u = H[base4 + b];
      unsigned bin = slice * SLICEB + (base4 + b) * 4;
      if (r < c2 + u.x){ s_bin = bin + 0; break; } c2 += u.x;
      if (r < c2 + u.y){ s_bin = bin + 1; break; } c2 += u.y;
      if (r < c2 + u.z){ s_bin = bin + 2; break; } c2 += u.z;
      if (r < c2 + u.w){ s_bin = bin + 3; break; } c2 += u.w;
    }
  }
  __syncthreads();
  unsigned v = s_bin;
  __syncthreads();
  return v;
}

// last-block ticket
__device__ __forceinline__ bool last_block(unsigned* tick, unsigned grid){
  __shared__ unsigned s_last;
  __syncthreads();
  __threadfence();
  if (threadIdx.x == 0){
    unsigned t = atomicAdd(tick, 1u);
    s_last = (t == grid - 1u) ? 1u : 0u;
  }
  __syncthreads();
  bool r = (s_last != 0u);
  if (r) __threadfence();
  return r;
}

// ---------------- pass 1: pack bytes + masked stats ----------------
__global__ void __launch_bounds__(256) k_stats(const float* __restrict__ img, int npix){
  __shared__ float lut[256];
  BUILD_LUT(lut);
  int n4 = npix >> 2;
  const float4* R  = (const float4*)img;
  const float4* Gp = R + n4;
  const float4* Bp = R + 2 * n4;
  uint4* PK = (uint4*)g_pack;
  float a[9] = {0,0,0,0,0,0,0,0,0};
  unsigned cnt = 0;
  int stride = gridDim.x * blockDim.x;
  for (int i = blockIdx.x * blockDim.x + threadIdx.x; i < n4; i += stride){
    float4 r = R[i], g = Gp[i], b = Bp[i];
    float rr[4] = {r.x, r.y, r.z, r.w};
    float gg[4] = {g.x, g.y, g.z, g.w};
    float bb[4] = {b.x, b.y, b.z, b.w};
    unsigned pk[4];
    #pragma unroll
    for (int j = 0; j < 4; j++){
      unsigned b0 = (unsigned)(int)(rr[j] * 255.0f);
      unsigned b1 = (unsigned)(int)(gg[j] * 255.0f);
      unsigned b2 = (unsigned)(int)(bb[j] * 255.0f);
      pk[j] = b0 | (b1 << 8) | (b2 << 16);
      float o0 = lut[b0], o1 = lut[b1], o2 = lut[b2];
      if (o0 >= 0.15f && o1 >= 0.15f && o2 >= 0.15f){
        a[0] += o0; a[1] += o1; a[2] += o2;
        a[3] += o0*o0; a[4] += o0*o1; a[5] += o0*o2;
        a[6] += o1*o1; a[7] += o1*o2; a[8] += o2*o2;
        cnt++;
      }
    }
    PK[i] = make_uint4(pk[0], pk[1], pk[2], pk[3]);
  }
  double d[9];
  #pragma unroll
  for (int k = 0; k < 9; k++) d[k] = (double)a[k];
  double c = (double)cnt;
  #pragma unroll
  for (int o = 16; o > 0; o >>= 1){
    #pragma unroll
    for (int k = 0; k < 9; k++) d[k] += __shfl_down_sync(0xffffffffu, d[k], o);
    c += __shfl_down_sync(0xffffffffu, c, o);
  }
  __shared__ double s_acc[10][8];
  int w = threadIdx.x >> 5, lane = threadIdx.x & 31;
  if (lane == 0){
    #pragma unroll
    for (int k = 0; k < 9; k++) s_acc[k][w] = d[k];
    s_acc[9][w] = c;
  }
  __syncthreads();
  if (threadIdx.x == 0){
    int nw = blockDim.x >> 5;
    double t[10] = {0,0,0,0,0,0,0,0,0,0};
    for (int ww = 0; ww < nw; ww++)
      for (int k = 0; k < 10; k++) t[k] += s_acc[k][ww];
    for (int k = 0; k < 9; k++) atomicAdd(&g_acc[k], t[k]);
    atomicAdd(&g_cnt, (unsigned long long)(t[9] + 0.5));
  }
}

// ---------------- pass 2: 3x3 eigh (double Jacobi, 1 thread) ----------------
__global__ void __launch_bounds__(32, 1) k_eig(){
  if (threadIdx.x != 0 || blockIdx.x != 0) return;
  double n = (double)g_cnt;
  double s0 = g_acc[0], s1 = g_acc[1], s2 = g_acc[2];
  double inv = 1.0 / (n - 1.0);
  double a[3][3];
  a[0][0] = (g_acc[3] - s0*s0/n) * inv;
  a[0][1] = a[1][0] = (g_acc[4] - s0*s1/n) * inv;
  a[0][2] = a[2][0] = (g_acc[5] - s0*s2/n) * inv;
  a[1][1] = (g_acc[6] - s1*s1/n) * inv;
  a[1][2] = a[2][1] = (g_acc[7] - s1*s2/n) * inv;
  a[2][2] = (g_acc[8] - s2*s2/n) * inv;
  double V[3][3] = {{1,0,0},{0,1,0},{0,0,1}};
  for (int sweep = 0; sweep < 30; sweep++){
    double off = fabs(a[0][1]) + fabs(a[0][2]) + fabs(a[1][2]);
    if (off < 1e-280) break;
    for (int p = 0; p < 2; p++){
      for (int q = p + 1; q < 3; q++){
        double apq = a[p][q];
        if (fabs(apq) < 1e-300) continue;
        double theta = (a[q][q] - a[p][p]) / (2.0 * apq);
        double t = (theta >= 0.0 ? 1.0 : -1.0) / (fabs(theta) + sqrt(theta*theta + 1.0));
        double c = 1.0 / sqrt(t*t + 1.0);
        double s = t * c;
        double app = a[p][p], aqq = a[q][q];
        a[p][p] = app - t * apq;
        a[q][q] = aqq + t * apq;
        a[p][q] = a[q][p] = 0.0;
        int r = 3 - p - q;
        double arp = a[r][p], arq = a[r][q];
        a[r][p] = a[p][r] = c*arp - s*arq;
        a[r][q] = a[q][r] = s*arp + c*arq;
        for (int k = 0; k < 3; k++){
          double vkp = V[k][p], vkq = V[k][q];
          V[k][p] = c*vkp - s*vkq;
          V[k][q] = s*vkp + c*vkq;
        }
      }
    }
  }
  double w[3] = {a[0][0], a[1][1], a[2][2]};
  int idx[3] = {0,1,2};
  for (int i = 0; i < 2; i++)
    for (int j = i + 1; j < 3; j++)
      if (w[idx[j]] < w[idx[i]]){ int tmp = idx[i]; idx[i] = idx[j]; idx[j] = tmp; }
  int cols[2] = {idx[1], idx[2]};
  for (int j = 0; j < 2; j++){
    double v0 = V[0][cols[j]], v1 = V[1][cols[j]], v2 = V[2][cols[j]];
    double mx = v0, mxa = fabs(v0);
    if (fabs(v1) > mxa){ mxa = fabs(v1); mx = v1; }
    if (fabs(v2) > mxa){ mxa = fabs(v2); mx = v2; }
    double sgn = (mx < 0.0) ? -1.0 : 1.0;
    g_E[3*j+0] = (float)(v0 * sgn);
    g_E[3*j+1] = (float)(v1 * sgn);
    g_E[3*j+2] = (float)(v2 * sgn);
  }
}

// ---------------- pass 3: phi linear histogram; tail = quantiles + HE solve ----------------
__global__ void __launch_bounds__(256) k_phiq(int npix){
  __shared__ unsigned sb[SLICES];
  __shared__ float lut[256];
  BUILD_LUT(lut);
  for (int b = threadIdx.x; b < SLICES; b += 256) sb[b] = 0u;
  __syncthreads();
  int n4 = npix >> 2;
  const uint4* PK = (const uint4*)g_pack;
  float e0=g_E[0],e1=g_E[1],e2=g_E[2],e3=g_E[3],e4=g_E[4],e5=g_E[5];
  int stride = gridDim.x * blockDim.x;
  for (int i = blockIdx.x * blockDim.x + threadIdx.x; i < n4; i += stride){
    uint4 u = PK[i];
    unsigned pk[4] = {u.x, u.y, u.z, u.w};
    #pragma unroll
    for (int j = 0; j < 4; j++){
      float o0 = lut[pk[j] & 255u], o1 = lut[(pk[j] >> 8) & 255u], o2 = lut[(pk[j] >> 16) & 255u];
      if (o0 >= 0.15f && o1 >= 0.15f && o2 >= 0.15f){
        float t0 = o0*e0 + o1*e1 + o2*e2;
        float t1 = o0*e3 + o1*e4 + o2*e5;
        int b = qbin(atan2f(t1, t0), PHI_LO, PHI_SCALE);
        atomicAdd(&g_hq[0][b], 1u);
        atomicAdd(&sb[b >> 14], 1u);
      }
    }
  }
  __syncthreads();
  for (int b = threadIdx.x; b < SLICES; b += 256){
    unsigned v = sb[b];
    if (v) atomicAdd(&g_bsum[0][b], v);
  }
  // ---- tail: resolve phi quantiles + HE solve ----
  if (last_block(&g_tick[0], gridDim.x)){
    __shared__ unsigned rk[4];
    __shared__ float fr[2];
    if (threadIdx.x == 0){
      unsigned n = (unsigned)g_cnt;
      float nm1 = (float)(n - 1u);
      float p0 = 0.01f * nm1, p1 = 0.99f * nm1;
      float l0 = floorf(p0), l1 = floorf(p1);
      rk[0] = (unsigned)l0; rk[1] = (unsigned)ceilf(p0);
      rk[2] = (unsigned)l1; rk[3] = (unsigned)ceilf(p1);
      fr[0] = p0 - l0; fr[1] = p1 - l1;
    }
    __syncthreads();
    float v[4];
    for (int q = 0; q < 4; q++){
      unsigned bin = resolve_bin(g_hq[0], g_bsum[0], rk[q]);
      v[q] = PHI_LO + ((float)bin + 0.5f) * PHI_INV;
    }
    if (threadIdx.x == 0){
      float minPhi = v[0] * (1.0f - fr[0]) + v[1] * fr[0];
      float maxPhi = v[2] * (1.0f - fr[1]) + v[3] * fr[1];
      float cmn = cosf(minPhi), smn = sinf(minPhi);
      float cmx = cosf(maxPhi), smx = sinf(maxPhi);
      float vMin[3], vMax[3];
      for (int i = 0; i < 3; i++){
        vMin[i] = g_E[i] * cmn + g_E[3 + i] * smn;
        vMax[i] = g_E[i] * cmx + g_E[3 + i] * smx;
      }
      float he[3][2];
      if (vMin[0] > vMax[0])
        for (int i = 0; i < 3; i++){ he[i][0] = vMin[i]; he[i][1] = vMax[i]; }
      else
        for (int i = 0; i < 3; i++){ he[i][0] = vMax[i]; he[i][1] = vMin[i]; }
      double m00 = 0, m01 = 0, m11 = 0;
      for (int i = 0; i < 3; i++){
        m00 += (double)he[i][0] * he[i][0];
        m01 += (double)he[i][0] * he[i][1];
        m11 += (double)he[i][1] * he[i][1];
      }
      double det = m00 * m11 - m01 * m01;
      double i00 = m11 / det, i01 = -m01 / det, i11 = m00 / det;
      for (int j = 0; j < 3; j++){
        g_A[j]     = (float)(i00 * he[j][0] + i01 * he[j][1]);
        g_A[3 + j] = (float)(i01 * he[j][0] + i11 * he[j][1]);
      }
      g_tick[0] = 0u;
    }
  }
}

// ---------------- pass 4: C linear histograms; tail = maxC + G fuse ----------------
__global__ void __launch_bounds__(256) k_Cq(const float* __restrict__ HERef,
                                            const float* __restrict__ maxCRef, int npix){
  __shared__ unsigned sb0[SLICES];
  __shared__ unsigned sb1[SLICES];
  __shared__ float lut[256];
  BUILD_LUT(lut);
  for (int b = threadIdx.x; b < SLICES; b += 256){ sb0[b] = 0u; sb1[b] = 0u; }
  __syncthreads();
  int n4 = npix >> 2;
  const uint4* PK = (const uint4*)g_pack;
  float a0=g_A[0],a1=g_A[1],a2=g_A[2],a3=g_A[3],a4=g_A[4],a5=g_A[5];
  int stride = gridDim.x * blockDim.x;
  for (int i = blockIdx.x * blockDim.x + threadIdx.x; i < n4; i += stride){
    uint4 u = PK[i];
    unsigned pk[4] = {u.x, u.y, u.z, u.w};
    #pragma unroll
    for (int j = 0; j < 4; j++){
      float o0 = lut[pk[j] & 255u], o1 = lut[(pk[j] >> 8) & 255u], o2 = lut[(pk[j] >> 16) & 255u];
      int b0 = qbin(o0*a0 + o1*a1 + o2*a2, C_LO, C_SCALE);
      int b1 = qbin(o0*a3 + o1*a4 + o2*a5, C_LO, C_SCALE);
      atomicAdd(&g_hq[1][b0], 1u);
      atomicAdd(&sb0[b0 >> 14], 1u);
      atomicAdd(&g_hq[2][b1], 1u);
      atomicAdd(&sb1[b1 >> 14], 1u);
    }
  }
  __syncthreads();
  for (int b = threadIdx.x; b < SLICES; b += 256){
    unsigned v0 = sb0[b]; if (v0) atomicAdd(&g_bsum[1][b], v0);
    unsigned v1 = sb1[b]; if (v1) atomicAdd(&g_bsum[2][b], v1);
  }
  // ---- tail: resolve maxC quantiles + G fuse ----
  if (last_block(&g_tick[1], gridDim.x)){
    __shared__ unsigned rk[2];
    __shared__ float fr;
    if (threadIdx.x == 0){
      float nm1 = (float)(npix - 1);
      float p = 0.99f * nm1;
      float l = floorf(p);
      rk[0] = (unsigned)l;
      rk[1] = (unsigned)ceilf(p);
      fr = p - l;
    }
    __syncthreads();
    float v[4];
    for (int q = 0; q < 2; q++){
      unsigned bin = resolve_bin(g_hq[1], g_bsum[1], rk[q]);
      v[q] = C_LO + ((float)bin + 0.5f) * C_INV;
    }
    for (int q = 0; q < 2; q++){
      unsigned bin = resolve_bin(g_hq[2], g_bsum[2], rk[q]);
      v[2 + q] = C_LO + ((float)bin + 0.5f) * C_INV;
    }
    if (threadIdx.x == 0){
      float maxC0 = v[0] * (1.0f - fr) + v[1] * fr;
      float maxC1 = v[2] * (1.0f - fr) + v[3] * fr;
      float s0 = maxCRef[0] / maxC0;
      float s1 = maxCRef[1] / maxC1;
      for (int i = 0; i < 3; i++)
        for (int j = 0; j < 3; j++)
          g_G[i * 3 + j] = HERef[i * 2 + 0] * s0 * g_A[j] + HERef[i * 2 + 1] * s1 * g_A[3 + j];
      g_tick[1] = 0u;
    }
  }
}

// ---------------- pass 5: final output; tail = zero scratch for next replay ----------------
__global__ void __launch_bounds__(256) k_final(float* __restrict__ out, int npix){
  __shared__ float lut[256];
  BUILD_LUT(lut);
  int n4 = npix >> 2;
  const uint4* PK = (const uint4*)g_pack;
  float4* O = (float4*)out;
  float G00=g_G[0],G01=g_G[1],G02=g_G[2];
  float G10=g_G[3],G11=g_G[4],G12=g_G[5];
  float G20=g_G[6],G21=g_G[7],G22=g_G[8];
  int tid = blockIdx.x * blockDim.x + threadIdx.x;
  int stride = gridDim.x * blockDim.x;
  for (int i = tid; i < n4; i += stride){
    uint4 u = PK[i];
    unsigned pk[4] = {u.x, u.y, u.z, u.w};
    float res[12];
    #pragma unroll
    for (int j = 0; j < 4; j++){
      float o0 = lut[pk[j] & 255u], o1 = lut[(pk[j] >> 8) & 255u], o2 = lut[(pk[j] >> 16) & 255u];
      float y0 = o0*G00 + o1*G01 + o2*G02;
      float y1 = o0*G10 + o1*G11 + o2*G12;
      float y2 = o0*G20 + o1*G21 + o2*G22;
      res[3*j+0] = floorf(fminf(240.0f * __expf(-y0), 255.0f)) * (1.0f / 255.0f);
      res[3*j+1] = floorf(fminf(240.0f * __expf(-y1), 255.0f)) * (1.0f / 255.0f);
      res[3*j+2] = floorf(fminf(240.0f * __expf(-y2), 255.0f)) * (1.0f / 255.0f);
    }
    O[3*i+0] = make_float4(res[0], res[1], res[2],  res[3]);
    O[3*i+1] = make_float4(res[4], res[5], res[6],  res[7]);
    O[3*i+2] = make_float4(res[8], res[9], res[10], res[11]);
  }
  // ---- tail: zero all scratch for next replay ----
  uint4 z = make_uint4(0, 0, 0, 0);
  uint4* B = (uint4*)&g_hq[0][0];
  int tot4 = (3 * QBINS) / 4;
  for (int i = tid; i < tot4; i += stride) B[i] = z;
  for (int i = tid; i < 3 * SLICES; i += stride) ((unsigned*)g_bsum)[i] = 0u;
  if (tid < 9) g_acc[tid] = 0.0;
  if (tid == 0) g_cnt = 0ull;
}

// ---------------- launch ----------------
extern "C" void kernel_launch(void* const* d_in, const int* in_sizes, int n_in,
                              void* d_out, int out_size) {
  const float* img     = (const float*)d_in[0];
  const float* HERef   = (const float*)d_in[1];
  const float* maxCRef = (const float*)d_in[2];
  float* out = (float*)d_out;
  int npix = in_sizes[0] / 3;

  k_stats <<<1024, 256>>>(img, npix);
  k_eig   <<<1, 32>>>();
  k_phiq  <<<1024, 256>>>(npix);
  k_Cq    <<<1024, 256>>>(HERef, maxCRef, npix);
  k_final <<<2048, 256>>>(out, npix);
}

// round 14
// speedup vs baseline: 1.4721x; 1.4721x over previous
#include <cuda_runtime.h>
#include <stdint.h>

#define MAXPIX 4194304
#define CBINS 4096          // coarse bins
#define FBINS 1024          // fine bins per coarse bin
#define TOT22 (4194304.0f)  // 2^22

// ---------------- device scratch (zero-initialized at load) ----------------
__device__ double             g_acc[9];
__device__ unsigned long long g_cnt;
__device__ unsigned           g_hc[3][CBINS];   // coarse hists: phi, C0, C1
__device__ unsigned           g_hf[8][FBINS];   // fine hists: 0..3 phi, 4..7 C
__device__ unsigned           g_pack[MAXPIX];
__device__ float              g_E[6];
__device__ float              g_A[6];
__device__ float              g_G[9];
__device__ unsigned           g_topbin[8];
__device__ unsigned           g_rankin[8];
__device__ float              g_frac[3];
__device__ unsigned           g_tick[4];

// ---------------- binning constants ----------------
#define PHI_LO   (-3.1415928f)
#define PHI_SPAN (6.2831856f)
#define C_LO     (-32.0f)
#define C_SPAN   (64.0f)

__device__ __forceinline__ int pos22(float x, float lo, float inv_span){
  int b = (int)((x - lo) * inv_span * TOT22);
  return min(max(b, 0), (1 << 22) - 1);
}

#define BUILD_LUT(lut) \
  do { \
    if (threadIdx.x < 256) \
      lut[threadIdx.x] = -__logf((float)(threadIdx.x + 1) * (1.0f / 240.0f)); \
    __syncthreads(); \
  } while (0)

// blockDim-generic exclusive scan
__device__ unsigned blk_exscan(unsigned v){
  __shared__ unsigned ws[32];
  int lane = threadIdx.x & 31, w = threadIdx.x >> 5;
  int nw = blockDim.x >> 5;
  unsigned x = v;
  #pragma unroll
  for (int o = 1; o < 32; o <<= 1){
    unsigned y = __shfl_up_sync(0xffffffffu, x, o);
    if (lane >= o) x += y;
  }
  if (lane == 31) ws[w] = x;
  __syncthreads();
  if (threadIdx.x < 32){
    unsigned t = (lane < nw) ? ws[lane] : 0u;
    #pragma unroll
    for (int o = 1; o < 32; o <<= 1){
      unsigned y = __shfl_up_sync(0xffffffffu, t, o);
      if (lane >= o) t += y;
    }
    ws[lane] = t;
  }
  __syncthreads();
  unsigned base = (w == 0) ? 0u : ws[w - 1];
  unsigned res = base + x - v;
  __syncthreads();
  return res;
}

// multi-rank k-th over an NB-bin histogram (block-collective); NB % blockDim == 0
// NOTE: out_bin/out_rib are written ONLY by the owning thread -> must point to
// shared or global memory; the trailing __syncthreads publishes them block-wide.
__device__ void find_kth(const unsigned* __restrict__ hist, int NB,
                         const unsigned* ranks, int nr,
                         unsigned* out_bin, unsigned* out_rib){
  int bpt = NB / blockDim.x;
  unsigned base = threadIdx.x * bpt;
  unsigned s = 0;
  for (int b = 0; b < bpt; b++) s += hist[base + b];
  unsigned cum = blk_exscan(s);
  for (int q = 0; q < nr; q++){
    unsigned rank = ranks[q];
    if (rank >= cum && rank < cum + s){
      unsigned c2 = cum;
      for (int b = 0; b < bpt; b++){
        unsigned h = hist[base + b];
        if (rank < c2 + h){ out_bin[q] = base + b; out_rib[q] = rank - c2; break; }
        c2 += h;
      }
    }
  }
  __syncthreads();
}

// last-block ticket
__device__ __forceinline__ bool last_block(unsigned* tick, unsigned grid){
  __shared__ unsigned s_last;
  __syncthreads();
  __threadfence();
  if (threadIdx.x == 0){
    unsigned t = atomicAdd(tick, 1u);
    s_last = (t == grid - 1u) ? 1u : 0u;
  }
  __syncthreads();
  bool r = (s_last != 0u);
  if (r) __threadfence();
  return r;
}

// ---------------- pass 1: pack bytes + masked stats ----------------
__global__ void __launch_bounds__(256) k_stats(const float* __restrict__ img, int npix){
  __shared__ float lut[256];
  BUILD_LUT(lut);
  int n4 = npix >> 2;
  const float4* R  = (const float4*)img;
  const float4* Gp = R + n4;
  const float4* Bp = R + 2 * n4;
  uint4* PK = (uint4*)g_pack;
  float a[9] = {0,0,0,0,0,0,0,0,0};
  unsigned cnt = 0;
  int stride = gridDim.x * blockDim.x;
  for (int i = blockIdx.x * blockDim.x + threadIdx.x; i < n4; i += stride){
    float4 r = R[i], g = Gp[i], b = Bp[i];
    float rr[4] = {r.x, r.y, r.z, r.w};
    float gg[4] = {g.x, g.y, g.z, g.w};
    float bb[4] = {b.x, b.y, b.z, b.w};
    unsigned pk[4];
    #pragma unroll
    for (int j = 0; j < 4; j++){
      unsigned b0 = (unsigned)(int)(rr[j] * 255.0f);
      unsigned b1 = (unsigned)(int)(gg[j] * 255.0f);
      unsigned b2 = (unsigned)(int)(bb[j] * 255.0f);
      pk[j] = b0 | (b1 << 8) | (b2 << 16);
      float o0 = lut[b0], o1 = lut[b1], o2 = lut[b2];
      if (o0 >= 0.15f && o1 >= 0.15f && o2 >= 0.15f){
        a[0] += o0; a[1] += o1; a[2] += o2;
        a[3] += o0*o0; a[4] += o0*o1; a[5] += o0*o2;
        a[6] += o1*o1; a[7] += o1*o2; a[8] += o2*o2;
        cnt++;
      }
    }
    PK[i] = make_uint4(pk[0], pk[1], pk[2], pk[3]);
  }
  double d[9];
  #pragma unroll
  for (int k = 0; k < 9; k++) d[k] = (double)a[k];
  double c = (double)cnt;
  #pragma unroll
  for (int o = 16; o > 0; o >>= 1){
    #pragma unroll
    for (int k = 0; k < 9; k++) d[k] += __shfl_down_sync(0xffffffffu, d[k], o);
    c += __shfl_down_sync(0xffffffffu, c, o);
  }
  __shared__ double s_acc[10][8];
  int w = threadIdx.x >> 5, lane = threadIdx.x & 31;
  if (lane == 0){
    #pragma unroll
    for (int k = 0; k < 9; k++) s_acc[k][w] = d[k];
    s_acc[9][w] = c;
  }
  __syncthreads();
  if (threadIdx.x == 0){
    int nw = blockDim.x >> 5;
    double t[10] = {0,0,0,0,0,0,0,0,0,0};
    for (int ww = 0; ww < nw; ww++)
      for (int k = 0; k < 10; k++) t[k] += s_acc[k][ww];
    for (int k = 0; k < 9; k++) atomicAdd(&g_acc[k], t[k]);
    atomicAdd(&g_cnt, (unsigned long long)(t[9] + 0.5));
  }
}

// ---------------- pass 2: 3x3 eigh ----------------
__global__ void __launch_bounds__(32, 1) k_eig(){
  if (threadIdx.x != 0 || blockIdx.x != 0) return;
  double n = (double)g_cnt;
  double s0 = g_acc[0], s1 = g_acc[1], s2 = g_acc[2];
  double inv = 1.0 / (n - 1.0);
  double a[3][3];
  a[0][0] = (g_acc[3] - s0*s0/n) * inv;
  a[0][1] = a[1][0] = (g_acc[4] - s0*s1/n) * inv;
  a[0][2] = a[2][0] = (g_acc[5] - s0*s2/n) * inv;
  a[1][1] = (g_acc[6] - s1*s1/n) * inv;
  a[1][2] = a[2][1] = (g_acc[7] - s1*s2/n) * inv;
  a[2][2] = (g_acc[8] - s2*s2/n) * inv;
  double V[3][3] = {{1,0,0},{0,1,0},{0,0,1}};
  for (int sweep = 0; sweep < 30; sweep++){
    double off = fabs(a[0][1]) + fabs(a[0][2]) + fabs(a[1][2]);
    if (off < 1e-280) break;
    for (int p = 0; p < 2; p++){
      for (int q = p + 1; q < 3; q++){
        double apq = a[p][q];
        if (fabs(apq) < 1e-300) continue;
        double theta = (a[q][q] - a[p][p]) / (2.0 * apq);
        double t = (theta >= 0.0 ? 1.0 : -1.0) / (fabs(theta) + sqrt(theta*theta + 1.0));
        double c = 1.0 / sqrt(t*t + 1.0);
        double s = t * c;
        double app = a[p][p], aqq = a[q][q];
        a[p][p] = app - t * apq;
        a[q][q] = aqq + t * apq;
        a[p][q] = a[q][p] = 0.0;
        int r = 3 - p - q;
        double arp = a[r][p], arq = a[r][q];
        a[r][p] = a[p][r] = c*arp - s*arq;
        a[r][q] = a[q][r] = s*arp + c*arq;
        for (int k = 0; k < 3; k++){
          double vkp = V[k][p], vkq = V[k][q];
          V[k][p] = c*vkp - s*vkq;
          V[k][q] = s*vkp + c*vkq;
        }
      }
    }
  }
  double w[3] = {a[0][0], a[1][1], a[2][2]};
  int idx[3] = {0,1,2};
  for (int i = 0; i < 2; i++)
    for (int j = i + 1; j < 3; j++)
      if (w[idx[j]] < w[idx[i]]){ int tmp = idx[i]; idx[i] = idx[j]; idx[j] = tmp; }
  int cols[2] = {idx[1], idx[2]};
  for (int j = 0; j < 2; j++){
    double v0 = V[0][cols[j]], v1 = V[1][cols[j]], v2 = V[2][cols[j]];
    double mx = v0, mxa = fabs(v0);
    if (fabs(v1) > mxa){ mxa = fabs(v1); mx = v1; }
    if (fabs(v2) > mxa){ mxa = fabs(v2); mx = v2; }
    double sgn = (mx < 0.0) ? -1.0 : 1.0;
    g_E[3*j+0] = (float)(v0 * sgn);
    g_E[3*j+1] = (float)(v1 * sgn);
    g_E[3*j+2] = (float)(v2 * sgn);
  }
}

// phi 22-bit position (identical in k_phiq / k_phir)
__device__ __forceinline__ int phi_pos(unsigned pk, const float* lut,
                                       float e0, float e1, float e2,
                                       float e3, float e4, float e5, bool& ok){
  float o0 = lut[pk & 255u], o1 = lut[(pk >> 8) & 255u], o2 = lut[(pk >> 16) & 255u];
  ok = (o0 >= 0.15f && o1 >= 0.15f && o2 >= 0.15f);
  if (!ok) return 0;
  float t0 = o0*e0 + o1*e1 + o2*e2;
  float t1 = o0*e3 + o1*e4 + o2*e5;
  return pos22(atan2f(t1, t0), PHI_LO, 1.0f / PHI_SPAN);
}

// C 22-bit positions (identical in k_Cq / k_Cr)
__device__ __forceinline__ void c_pos(unsigned pk, const float* lut,
                                      float a0, float a1, float a2,
                                      float a3, float a4, float a5,
                                      int& p0, int& p1){
  float o0 = lut[pk & 255u], o1 = lut[(pk >> 8) & 255u], o2 = lut[(pk >> 16) & 255u];
  p0 = pos22(o0*a0 + o1*a1 + o2*a2, C_LO, 1.0f / C_SPAN);
  p1 = pos22(o0*a3 + o1*a4 + o2*a5, C_LO, 1.0f / C_SPAN);
}

// ---------------- pass 3: phi coarse hist; tail = coarse rank resolve ----------------
__global__ void __launch_bounds__(256) k_phiq(int npix){
  __shared__ unsigned sh[CBINS];
  __shared__ float lut[256];
  BUILD_LUT(lut);
  for (int b = threadIdx.x; b < CBINS; b += 256) sh[b] = 0u;
  __syncthreads();
  int n4 = npix >> 2;
  const uint4* PK = (const uint4*)g_pack;
  float e0=g_E[0],e1=g_E[1],e2=g_E[2],e3=g_E[3],e4=g_E[4],e5=g_E[5];
  int stride = gridDim.x * blockDim.x;
  for (int i = blockIdx.x * blockDim.x + threadIdx.x; i < n4; i += stride){
    uint4 u = PK[i];
    unsigned pk[4] = {u.x, u.y, u.z, u.w};
    #pragma unroll
    for (int j = 0; j < 4; j++){
      bool ok;
      int ff = phi_pos(pk[j], lut, e0,e1,e2,e3,e4,e5, ok);
      if (ok) atomicAdd(&sh[ff >> 10], 1u);
    }
  }
  __syncthreads();
  for (int b = threadIdx.x; b < CBINS; b += 256){
    unsigned v = sh[b];
    if (v) atomicAdd(&g_hc[0][b], v);
  }
  if (last_block(&g_tick[0], gridDim.x)){
    __shared__ unsigned rk[4];
    if (threadIdx.x == 0){
      unsigned n = (unsigned)g_cnt;
      float nm1 = (float)(n - 1u);
      float p0 = 0.01f * nm1, p1 = 0.99f * nm1;
      float l0 = floorf(p0), l1 = floorf(p1);
      rk[0] = (unsigned)l0; rk[1] = (unsigned)ceilf(p0);
      rk[2] = (unsigned)l1; rk[3] = (unsigned)ceilf(p1);
      g_frac[0] = p0 - l0; g_frac[1] = p1 - l1;
    }
    __syncthreads();
    find_kth(g_hc[0], CBINS, rk, 4, &g_topbin[0], &g_rankin[0]);
    if (threadIdx.x == 0) g_tick[0] = 0u;
  }
}

// ---------------- pass 4: phi fine hists; tail = fine resolve + HE solve ----------------
__global__ void __launch_bounds__(256) k_phir(int npix){
  __shared__ unsigned fh[4][FBINS];
  __shared__ float lut[256];
  BUILD_LUT(lut);
  for (int b = threadIdx.x; b < 4 * FBINS; b += 256) ((unsigned*)fh)[b] = 0u;
  __syncthreads();
  int n4 = npix >> 2;
  const uint4* PK = (const uint4*)g_pack;
  float e0=g_E[0],e1=g_E[1],e2=g_E[2],e3=g_E[3],e4=g_E[4],e5=g_E[5];
  int tb0 = (int)g_topbin[0], tb1 = (int)g_topbin[1], tb2 = (int)g_topbin[2], tb3 = (int)g_topbin[3];
  int stride = gridDim.x * blockDim.x;
  for (int i = blockIdx.x * blockDim.x + threadIdx.x; i < n4; i += stride){
    uint4 u = PK[i];
    unsigned pk[4] = {u.x, u.y, u.z, u.w};
    #pragma unroll
    for (int j = 0; j < 4; j++){
      bool ok;
      int ff = phi_pos(pk[j], lut, e0,e1,e2,e3,e4,e5, ok);
      if (ok){
        int cb = ff >> 10, fb = ff & (FBINS - 1);
        if (cb == tb0) atomicAdd(&fh[0][fb], 1u);
        if (cb == tb1) atomicAdd(&fh[1][fb], 1u);
        if (cb == tb2) atomicAdd(&fh[2][fb], 1u);
        if (cb == tb3) atomicAdd(&fh[3][fb], 1u);
      }
    }
  }
  __syncthreads();
  for (int b = threadIdx.x; b < 4 * FBINS; b += 256){
    unsigned v = ((unsigned*)fh)[b];
    if (v) atomicAdd(&((unsigned*)g_hf)[b], v);
  }
  if (last_block(&g_tick[1], gridDim.x)){
    __shared__ unsigned s_fb[4], s_rib[4];   // SHARED: published by find_kth's sync
    for (int q = 0; q < 4; q++)
      find_kth(g_hf[q], FBINS, &g_rankin[q], 1, &s_fb[q], &s_rib[q]);
    if (threadIdx.x == 0){
      float v[4];
      for (int q = 0; q < 4; q++)
        v[q] = PHI_LO + (((float)((g_topbin[q] << 10) | s_fb[q])) + 0.5f) * (PHI_SPAN / TOT22);
      float f0 = g_frac[0], f1 = g_frac[1];
      float minPhi = v[0] * (1.0f - f0) + v[1] * f0;
      float maxPhi = v[2] * (1.0f - f1) + v[3] * f1;
      float cmn = cosf(minPhi), smn = sinf(minPhi);
      float cmx = cosf(maxPhi), smx = sinf(maxPhi);
      float vMin[3], vMax[3];
      for (int i = 0; i < 3; i++){
        vMin[i] = g_E[i] * cmn + g_E[3 + i] * smn;
        vMax[i] = g_E[i] * cmx + g_E[3 + i] * smx;
      }
      float he[3][2];
      if (vMin[0] > vMax[0])
        for (int i = 0; i < 3; i++){ he[i][0] = vMin[i]; he[i][1] = vMax[i]; }
      else
        for (int i = 0; i < 3; i++){ he[i][0] = vMax[i]; he[i][1] = vMin[i]; }
      double m00 = 0, m01 = 0, m11 = 0;
      for (int i = 0; i < 3; i++){
        m00 += (double)he[i][0] * he[i][0];
        m01 += (double)he[i][0] * he[i][1];
        m11 += (double)he[i][1] * he[i][1];
      }
      double det = m00 * m11 - m01 * m01;
      double i00 = m11 / det, i01 = -m01 / det, i11 = m00 / det;
      for (int j = 0; j < 3; j++){
        g_A[j]     = (float)(i00 * he[j][0] + i01 * he[j][1]);
        g_A[3 + j] = (float)(i01 * he[j][0] + i11 * he[j][1]);
      }
      g_tick[1] = 0u;
    }
  }
}

// ---------------- pass 5: C coarse hists; tail = coarse rank resolve ----------------
__global__ void __launch_bounds__(256) k_Cq(int npix){
  __shared__ unsigned sh0[CBINS];
  __shared__ unsigned sh1[CBINS];
  __shared__ float lut[256];
  BUILD_LUT(lut);
  for (int b = threadIdx.x; b < CBINS; b += 256){ sh0[b] = 0u; sh1[b] = 0u; }
  __syncthreads();
  int n4 = npix >> 2;
  const uint4* PK = (const uint4*)g_pack;
  float a0=g_A[0],a1=g_A[1],a2=g_A[2],a3=g_A[3],a4=g_A[4],a5=g_A[5];
  int stride = gridDim.x * blockDim.x;
  for (int i = blockIdx.x * blockDim.x + threadIdx.x; i < n4; i += stride){
    uint4 u = PK[i];
    unsigned pk[4] = {u.x, u.y, u.z, u.w};
    #pragma unroll
    for (int j = 0; j < 4; j++){
      int p0, p1;
      c_pos(pk[j], lut, a0,a1,a2,a3,a4,a5, p0, p1);
      atomicAdd(&sh0[p0 >> 10], 1u);
      atomicAdd(&sh1[p1 >> 10], 1u);
    }
  }
  __syncthreads();
  for (int b = threadIdx.x; b < CBINS; b += 256){
    unsigned v0 = sh0[b]; if (v0) atomicAdd(&g_hc[1][b], v0);
    unsigned v1 = sh1[b]; if (v1) atomicAdd(&g_hc[2][b], v1);
  }
  if (last_block(&g_tick[2], gridDim.x)){
    __shared__ unsigned rk[2];
    if (threadIdx.x == 0){
      float nm1 = (float)(npix - 1);
      float p = 0.99f * nm1;
      float l = floorf(p);
      rk[0] = (unsigned)l;
      rk[1] = (unsigned)ceilf(p);
      g_frac[2] = p - l;
    }
    __syncthreads();
    find_kth(g_hc[1], CBINS, rk, 2, &g_topbin[4], &g_rankin[4]);
    find_kth(g_hc[2], CBINS, rk, 2, &g_topbin[6], &g_rankin[6]);
    if (threadIdx.x == 0) g_tick[2] = 0u;
  }
}

// ---------------- pass 6: C fine hists; tail = fine resolve + G fuse ----------------
__global__ void __launch_bounds__(256) k_Cr(const float* __restrict__ HERef,
                                            const float* __restrict__ maxCRef, int npix){
  __shared__ unsigned fh[4][FBINS];
  __shared__ float lut[256];
  BUILD_LUT(lut);
  for (int b = threadIdx.x; b < 4 * FBINS; b += 256) ((unsigned*)fh)[b] = 0u;
  __syncthreads();
  int n4 = npix >> 2;
  const uint4* PK = (const uint4*)g_pack;
  float a0=g_A[0],a1=g_A[1],a2=g_A[2],a3=g_A[3],a4=g_A[4],a5=g_A[5];
  int tb4 = (int)g_topbin[4], tb5 = (int)g_topbin[5], tb6 = (int)g_topbin[6], tb7 = (int)g_topbin[7];
  int stride = gridDim.x * blockDim.x;
  for (int i = blockIdx.x * blockDim.x + threadIdx.x; i < n4; i += stride){
    uint4 u = PK[i];
    unsigned pk[4] = {u.x, u.y, u.z, u.w};
    #pragma unroll
    for (int j = 0; j < 4; j++){
      int p0, p1;
      c_pos(pk[j], lut, a0,a1,a2,a3,a4,a5, p0, p1);
      int cb0 = p0 >> 10, fb0 = p0 & (FBINS - 1);
      int cb1 = p1 >> 10, fb1 = p1 & (FBINS - 1);
      if (cb0 == tb4) atomicAdd(&fh[0][fb0], 1u);
      if (cb0 == tb5) atomicAdd(&fh[1][fb0], 1u);
      if (cb1 == tb6) atomicAdd(&fh[2][fb1], 1u);
      if (cb1 == tb7) atomicAdd(&fh[3][fb1], 1u);
    }
  }
  __syncthreads();
  for (int b = threadIdx.x; b < 4 * FBINS; b += 256){
    unsigned v = ((unsigned*)fh)[b];
    if (v) atomicAdd(&((unsigned*)g_hf)[4 * FBINS + b], v);
  }
  if (last_block(&g_tick[3], gridDim.x)){
    __shared__ unsigned s_fb[4], s_rib[4];   // SHARED: published by find_kth's sync
    for (int q = 0; q < 4; q++)
      find_kth(g_hf[4 + q], FBINS, &g_rankin[4 + q], 1, &s_fb[q], &s_rib[q]);
    if (threadIdx.x == 0){
      float v[4];
      for (int q = 0; q < 4; q++)
        v[q] = C_LO + (((float)((g_topbin[4 + q] << 10) | s_fb[q])) + 0.5f) * (C_SPAN / TOT22);
      float fc = g_frac[2];
      float maxC0 = v[0] * (1.0f - fc) + v[1] * fc;
      float maxC1 = v[2] * (1.0f - fc) + v[3] * fc;
      float s0 = maxCRef[0] / maxC0;
      float s1 = maxCRef[1] / maxC1;
      for (int i = 0; i < 3; i++)
        for (int j = 0; j < 3; j++)
          g_G[i * 3 + j] = HERef[i * 2 + 0] * s0 * g_A[j] + HERef[i * 2 + 1] * s1 * g_A[3 + j];
      g_tick[3] = 0u;
    }
  }
}

// ---------------- pass 7: final output; tail = zero scratch ----------------
__global__ void __launch_bounds__(256) k_final(float* __restrict__ out, int npix){
  __shared__ float lut[256];
  BUILD_LUT(lut);
  int n4 = npix >> 2;
  const uint4* PK = (const uint4*)g_pack;
  float4* O = (float4*)out;
  float G00=g_G[0],G01=g_G[1],G02=g_G[2];
  float G10=g_G[3],G11=g_G[4],G12=g_G[5];
  float G20=g_G[6],G21=g_G[7],G22=g_G[8];
  int tid = blockIdx.x * blockDim.x + threadIdx.x;
  int stride = gridDim.x * blockDim.x;
  for (int i = tid; i < n4; i += stride){
    uint4 u = PK[i];
    unsigned pk[4] = {u.x, u.y, u.z, u.w};
    float res[12];
    #pragma unroll
    for (int j = 0; j < 4; j++){
      float o0 = lut[pk[j] & 255u], o1 = lut[(pk[j] >> 8) & 255u], o2 = lut[(pk[j] >> 16) & 255u];
      float y0 = o0*G00 + o1*G01 + o2*G02;
      float y1 = o0*G10 + o1*G11 + o2*G12;
      float y2 = o0*G20 + o1*G21 + o2*G22;
      res[3*j+0] = floorf(fminf(240.0f * __expf(-y0), 255.0f)) * (1.0f / 255.0f);
      res[3*j+1] = floorf(fminf(240.0f * __expf(-y1), 255.0f)) * (1.0f / 255.0f);
      res[3*j+2] = floorf(fminf(240.0f * __expf(-y2), 255.0f)) * (1.0f / 255.0f);
    }
    O[3*i+0] = make_float4(res[0], res[1], res[2],  res[3]);
    O[3*i+1] = make_float4(res[4], res[5], res[6],  res[7]);
    O[3*i+2] = make_float4(res[8], res[9], res[10], res[11]);
  }
  // zero scratch for next replay (tiny: ~80 KB)
  for (int i = tid; i < 3 * CBINS; i += stride) ((unsigned*)g_hc)[i] = 0u;
  for (int i = tid; i < 8 * FBINS; i += stride) ((unsigned*)g_hf)[i] = 0u;
  if (tid < 9) g_acc[tid] = 0.0;
  if (tid == 0) g_cnt = 0ull;
}

// ---------------- launch ----------------
extern "C" void kernel_launch(void* const* d_in, const int* in_sizes, int n_in,
                              void* d_out, int out_size) {
  const float* img     = (const float*)d_in[0];
  const float* HERef   = (const float*)d_in[1];
  const float* maxCRef = (const float*)d_in[2];
  float* out = (float*)d_out;
  int npix = in_sizes[0] / 3;

  k_stats <<<1024, 256>>>(img, npix);
  k_eig   <<<1, 32>>>();
  k_phiq  <<<1024, 256>>>(npix);
  k_phir  <<<1024, 256>>>(npix);
  k_Cq    <<<1024, 256>>>(npix);
  k_Cr    <<<1024, 256>>>(HERef, maxCRef, npix);
  k_final <<<2048, 256>>>(out, npix);
}

// round 16
// speedup vs baseline: 1.5142x; 1.0286x over previous
#include <cuda_runtime.h>
#include <stdint.h>

#define MAXPIX 4194304
#define CBINS 4096          // coarse bins
#define FBINS 1024          // fine bins per coarse bin
#define TOT22 (4194304.0f)  // 2^22

// ---------------- device scratch (zero-initialized at load) ----------------
__device__ double             g_acc[9];
__device__ unsigned long long g_cnt;
__device__ unsigned           g_hc[3][CBINS];   // coarse hists: phi, C0, C1
__device__ unsigned           g_hf[8][FBINS];   // fine hists: 0..3 phi, 4..7 C
__device__ unsigned           g_pack[MAXPIX];   // packed byte triples
__device__ unsigned           g_pos[MAXPIX];    // cached phi 22-bit positions
__device__ float              g_E[6];
__device__ float              g_A[6];
__device__ float              g_G[9];
__device__ unsigned           g_topbin[8];
__device__ unsigned           g_rankin[8];
__device__ float              g_frac[3];
__device__ unsigned           g_tick[4];

// ---------------- binning constants ----------------
#define PHI_LO   (-3.1415928f)
#define PHI_SPAN (6.2831856f)
#define C_LO     (-32.0f)
#define C_SPAN   (64.0f)
#define MASKB    205u        // byte <= 205  <=>  OD >= 0.15 (exact)

__device__ __forceinline__ int pos22(float x, float lo, float inv_span){
  int b = (int)((x - lo) * inv_span * TOT22);
  return min(max(b, 0), (1 << 22) - 1);
}

#define BUILD_LUT(lut) \
  do { \
    if (threadIdx.x < 256) \
      lut[threadIdx.x] = -__logf((float)(threadIdx.x + 1) * (1.0f / 240.0f)); \
    __syncthreads(); \
  } while (0)

// additive C-position LUTs: p = (int)(cl0[b0]+cl1[b1]+cl2[b2]) ; offset folded in cl2
#define BUILD_CLUT(cl0, cl1, cl2, cl3, cl4, cl5, a0, a1, a2, a3, a4, a5) \
  do { \
    if (threadIdx.x < 256){ \
      float od = -__logf((float)(threadIdx.x + 1) * (1.0f / 240.0f)); \
      float S = (1.0f / C_SPAN) * TOT22; \
      cl0[threadIdx.x] = od * (a0) * S; \
      cl1[threadIdx.x] = od * (a1) * S; \
      cl2[threadIdx.x] = od * (a2) * S - C_LO * S; \
      cl3[threadIdx.x] = od * (a3) * S; \
      cl4[threadIdx.x] = od * (a4) * S; \
      cl5[threadIdx.x] = od * (a5) * S - C_LO * S; \
    } \
    __syncthreads(); \
  } while (0)

__device__ __forceinline__ int clamp22(float f){
  int b = (int)f;
  return min(max(b, 0), (1 << 22) - 1);
}

// blockDim-generic exclusive scan
__device__ unsigned blk_exscan(unsigned v){
  __shared__ unsigned ws[32];
  int lane = threadIdx.x & 31, w = threadIdx.x >> 5;
  int nw = blockDim.x >> 5;
  unsigned x = v;
  #pragma unroll
  for (int o = 1; o < 32; o <<= 1){
    unsigned y = __shfl_up_sync(0xffffffffu, x, o);
    if (lane >= o) x += y;
  }
  if (lane == 31) ws[w] = x;
  __syncthreads();
  if (threadIdx.x < 32){
    unsigned t = (lane < nw) ? ws[lane] : 0u;
    #pragma unroll
    for (int o = 1; o < 32; o <<= 1){
      unsigned y = __shfl_up_sync(0xffffffffu, t, o);
      if (lane >= o) t += y;
    }
    ws[lane] = t;
  }
  __syncthreads();
  unsigned base = (w == 0) ? 0u : ws[w - 1];
  unsigned res = base + x - v;
  __syncthreads();
  return res;
}

// multi-rank k-th over an NB-bin histogram (block-collective); NB % blockDim == 0
// out_bin/out_rib written only by owning thread -> must be shared/global;
// trailing __syncthreads publishes them.
__device__ void find_kth(const unsigned* __restrict__ hist, int NB,
                         const unsigned* ranks, int nr,
                         unsigned* out_bin, unsigned* out_rib){
  int bpt = NB / blockDim.x;
  unsigned base = threadIdx.x * bpt;
  unsigned s = 0;
  for (int b = 0; b < bpt; b++) s += hist[base + b];
  unsigned cum = blk_exscan(s);
  for (int q = 0; q < nr; q++){
    unsigned rank = ranks[q];
    if (rank >= cum && rank < cum + s){
      unsigned c2 = cum;
      for (int b = 0; b < bpt; b++){
        unsigned h = hist[base + b];
        if (rank < c2 + h){ out_bin[q] = base + b; out_rib[q] = rank - c2; break; }
        c2 += h;
      }
    }
  }
  __syncthreads();
}

// last-block ticket
__device__ __forceinline__ bool last_block(unsigned* tick, unsigned grid){
  __shared__ unsigned s_last;
  __syncthreads();
  __threadfence();
  if (threadIdx.x == 0){
    unsigned t = atomicAdd(tick, 1u);
    s_last = (t == grid - 1u) ? 1u : 0u;
  }
  __syncthreads();
  bool r = (s_last != 0u);
  if (r) __threadfence();
  return r;
}

// ---------------- pass 1: pack bytes + masked stats ----------------
__global__ void __launch_bounds__(256) k_stats(const float* __restrict__ img, int npix){
  __shared__ float lut[256];
  BUILD_LUT(lut);
  int n4 = npix >> 2;
  const float4* R  = (const float4*)img;
  const float4* Gp = R + n4;
  const float4* Bp = R + 2 * n4;
  uint4* PK = (uint4*)g_pack;
  float a[9] = {0,0,0,0,0,0,0,0,0};
  unsigned cnt = 0;
  int stride = gridDim.x * blockDim.x;
  for (int i = blockIdx.x * blockDim.x + threadIdx.x; i < n4; i += stride){
    float4 r = R[i], g = Gp[i], b = Bp[i];
    float rr[4] = {r.x, r.y, r.z, r.w};
    float gg[4] = {g.x, g.y, g.z, g.w};
    float bb[4] = {b.x, b.y, b.z, b.w};
    unsigned pk[4];
    #pragma unroll
    for (int j = 0; j < 4; j++){
      unsigned b0 = (unsigned)(int)(rr[j] * 255.0f);
      unsigned b1 = (unsigned)(int)(gg[j] * 255.0f);
      unsigned b2 = (unsigned)(int)(bb[j] * 255.0f);
      pk[j] = b0 | (b1 << 8) | (b2 << 16);
      if (b0 <= MASKB && b1 <= MASKB && b2 <= MASKB){
        float o0 = lut[b0], o1 = lut[b1], o2 = lut[b2];
        a[0] += o0; a[1] += o1; a[2] += o2;
        a[3] += o0*o0; a[4] += o0*o1; a[5] += o0*o2;
        a[6] += o1*o1; a[7] += o1*o2; a[8] += o2*o2;
        cnt++;
      }
    }
    PK[i] = make_uint4(pk[0], pk[1], pk[2], pk[3]);
  }
  double d[9];
  #pragma unroll
  for (int k = 0; k < 9; k++) d[k] = (double)a[k];
  double c = (double)cnt;
  #pragma unroll
  for (int o = 16; o > 0; o >>= 1){
    #pragma unroll
    for (int k = 0; k < 9; k++) d[k] += __shfl_down_sync(0xffffffffu, d[k], o);
    c += __shfl_down_sync(0xffffffffu, c, o);
  }
  __shared__ double s_acc[10][8];
  int w = threadIdx.x >> 5, lane = threadIdx.x & 31;
  if (lane == 0){
    #pragma unroll
    for (int k = 0; k < 9; k++) s_acc[k][w] = d[k];
    s_acc[9][w] = c;
  }
  __syncthreads();
  if (threadIdx.x == 0){
    int nw = blockDim.x >> 5;
    double t[10] = {0,0,0,0,0,0,0,0,0,0};
    for (int ww = 0; ww < nw; ww++)
      for (int k = 0; k < 10; k++) t[k] += s_acc[k][ww];
    for (int k = 0; k < 9; k++) atomicAdd(&g_acc[k], t[k]);
    atomicAdd(&g_cnt, (unsigned long long)(t[9] + 0.5));
  }
}

// ---------------- pass 2: 3x3 eigh ----------------
__global__ void __launch_bounds__(32, 1) k_eig(){
  if (threadIdx.x != 0 || blockIdx.x != 0) return;
  double n = (double)g_cnt;
  double s0 = g_acc[0], s1 = g_acc[1], s2 = g_acc[2];
  double inv = 1.0 / (n - 1.0);
  double a[3][3];
  a[0][0] = (g_acc[3] - s0*s0/n) * inv;
  a[0][1] = a[1][0] = (g_acc[4] - s0*s1/n) * inv;
  a[0][2] = a[2][0] = (g_acc[5] - s0*s2/n) * inv;
  a[1][1] = (g_acc[6] - s1*s1/n) * inv;
  a[1][2] = a[2][1] = (g_acc[7] - s1*s2/n) * inv;
  a[2][2] = (g_acc[8] - s2*s2/n) * inv;
  double V[3][3] = {{1,0,0},{0,1,0},{0,0,1}};
  for (int sweep = 0; sweep < 30; sweep++){
    double off = fabs(a[0][1]) + fabs(a[0][2]) + fabs(a[1][2]);
    if (off < 1e-280) break;
    for (int p = 0; p < 2; p++){
      for (int q = p + 1; q < 3; q++){
        double apq = a[p][q];
        if (fabs(apq) < 1e-300) continue;
        double theta = (a[q][q] - a[p][p]) / (2.0 * apq);
        double t = (theta >= 0.0 ? 1.0 : -1.0) / (fabs(theta) + sqrt(theta*theta + 1.0));
        double c = 1.0 / sqrt(t*t + 1.0);
        double s = t * c;
        double app = a[p][p], aqq = a[q][q];
        a[p][p] = app - t * apq;
        a[q][q] = aqq + t * apq;
        a[p][q] = a[q][p] = 0.0;
        int r = 3 - p - q;
        double arp = a[r][p], arq = a[r][q];
        a[r][p] = a[p][r] = c*arp - s*arq;
        a[r][q] = a[q][r] = s*arp + c*arq;
        for (int k = 0; k < 3; k++){
          double vkp = V[k][p], vkq = V[k][q];
          V[k][p] = c*vkp - s*vkq;
          V[k][q] = s*vkp + c*vkq;
        }
      }
    }
  }
  double w[3] = {a[0][0], a[1][1], a[2][2]};
  int idx[3] = {0,1,2};
  for (int i = 0; i < 2; i++)
    for (int j = i + 1; j < 3; j++)
      if (w[idx[j]] < w[idx[i]]){ int tmp = idx[i]; idx[i] = idx[j]; idx[j] = tmp; }
  int cols[2] = {idx[1], idx[2]};
  for (int j = 0; j < 2; j++){
    double v0 = V[0][cols[j]], v1 = V[1][cols[j]], v2 = V[2][cols[j]];
    double mx = v0, mxa = fabs(v0);
    if (fabs(v1) > mxa){ mxa = fabs(v1); mx = v1; }
    if (fabs(v2) > mxa){ mxa = fabs(v2); mx = v2; }
    double sgn = (mx < 0.0) ? -1.0 : 1.0;
    g_E[3*j+0] = (float)(v0 * sgn);
    g_E[3*j+1] = (float)(v1 * sgn);
    g_E[3*j+2] = (float)(v2 * sgn);
  }
}

// ---------------- pass 3: phi positions + coarse hist; tail = coarse resolve ----------------
__global__ void __launch_bounds__(256) k_phiq(int npix){
  __shared__ unsigned sh[CBINS];
  __shared__ float lut[256];
  BUILD_LUT(lut);
  for (int b = threadIdx.x; b < CBINS; b += 256) sh[b] = 0u;
  __syncthreads();
  int n4 = npix >> 2;
  const uint4* PK = (const uint4*)g_pack;
  uint4* PO = (uint4*)g_pos;
  float e0=g_E[0],e1=g_E[1],e2=g_E[2],e3=g_E[3],e4=g_E[4],e5=g_E[5];
  int stride = gridDim.x * blockDim.x;
  for (int i = blockIdx.x * blockDim.x + threadIdx.x; i < n4; i += stride){
    uint4 u = PK[i];
    unsigned pk[4] = {u.x, u.y, u.z, u.w};
    unsigned po[4];
    #pragma unroll
    for (int j = 0; j < 4; j++){
      unsigned b0 = pk[j] & 255u, b1 = (pk[j] >> 8) & 255u, b2 = (pk[j] >> 16) & 255u;
      if (b0 <= MASKB && b1 <= MASKB && b2 <= MASKB){
        float o0 = lut[b0], o1 = lut[b1], o2 = lut[b2];
        float t0 = o0*e0 + o1*e1 + o2*e2;
        float t1 = o0*e3 + o1*e4 + o2*e5;
        int ff = pos22(atan2f(t1, t0), PHI_LO, 1.0f / PHI_SPAN);
        po[j] = (unsigned)ff;
        atomicAdd(&sh[ff >> 10], 1u);
      } else {
        po[j] = 0xFFFFFFFFu;   // never matches any coarse bin
      }
    }
    PO[i] = make_uint4(po[0], po[1], po[2], po[3]);
  }
  __syncthreads();
  for (int b = threadIdx.x; b < CBINS; b += 256){
    unsigned v = sh[b];
    if (v) atomicAdd(&g_hc[0][b], v);
  }
  if (last_block(&g_tick[0], gridDim.x)){
    __shared__ unsigned rk[4];
    if (threadIdx.x == 0){
      unsigned n = (unsigned)g_cnt;
      float nm1 = (float)(n - 1u);
      float p0 = 0.01f * nm1, p1 = 0.99f * nm1;
      float l0 = floorf(p0), l1 = floorf(p1);
      rk[0] = (unsigned)l0; rk[1] = (unsigned)ceilf(p0);
      rk[2] = (unsigned)l1; rk[3] = (unsigned)ceilf(p1);
      g_frac[0] = p0 - l0; g_frac[1] = p1 - l1;
    }
    __syncthreads();
    find_kth(g_hc[0], CBINS, rk, 4, &g_topbin[0], &g_rankin[0]);
    if (threadIdx.x == 0) g_tick[0] = 0u;
  }
}

// ---------------- pass 4: phi fine hists from cached positions; tail = HE solve ----------------
__global__ void __launch_bounds__(256) k_phir(int npix){
  __shared__ unsigned fh[4][FBINS];
  for (int b = threadIdx.x; b < 4 * FBINS; b += 256) ((unsigned*)fh)[b] = 0u;
  __syncthreads();
  int n4 = npix >> 2;
  const uint4* PO = (const uint4*)g_pos;
  unsigned tb0 = g_topbin[0], tb1 = g_topbin[1], tb2 = g_topbin[2], tb3 = g_topbin[3];
  int stride = gridDim.x * blockDim.x;
  for (int i = blockIdx.x * blockDim.x + threadIdx.x; i < n4; i += stride){
    uint4 u = PO[i];
    unsigned po[4] = {u.x, u.y, u.z, u.w};
    #pragma unroll
    for (int j = 0; j < 4; j++){
      unsigned cb = po[j] >> 10, fb = po[j] & (FBINS - 1);
      if (cb == tb0) atomicAdd(&fh[0][fb], 1u);
      if (cb == tb1) atomicAdd(&fh[1][fb], 1u);
      if (cb == tb2) atomicAdd(&fh[2][fb], 1u);
      if (cb == tb3) atomicAdd(&fh[3][fb], 1u);
    }
  }
  __syncthreads();
  for (int b = threadIdx.x; b < 4 * FBINS; b += 256){
    unsigned v = ((unsigned*)fh)[b];
    if (v) atomicAdd(&((unsigned*)g_hf)[b], v);
  }
  if (last_block(&g_tick[1], gridDim.x)){
    __shared__ unsigned s_fb[4], s_rib[4];
    for (int q = 0; q < 4; q++)
      find_kth(g_hf[q], FBINS, &g_rankin[q], 1, &s_fb[q], &s_rib[q]);
    if (threadIdx.x == 0){
      float v[4];
      for (int q = 0; q < 4; q++)
        v[q] = PHI_LO + (((float)((g_topbin[q] << 10) | s_fb[q])) + 0.5f) * (PHI_SPAN / TOT22);
      float f0 = g_frac[0], f1 = g_frac[1];
      float minPhi = v[0] * (1.0f - f0) + v[1] * f0;
      float maxPhi = v[2] * (1.0f - f1) + v[3] * f1;
      float cmn = cosf(minPhi), smn = sinf(minPhi);
      float cmx = cosf(maxPhi), smx = sinf(maxPhi);
      float vMin[3], vMax[3];
      for (int i = 0; i < 3; i++){
        vMin[i] = g_E[i] * cmn + g_E[3 + i] * smn;
        vMax[i] = g_E[i] * cmx + g_E[3 + i] * smx;
      }
      float he[3][2];
      if (vMin[0] > vMax[0])
        for (int i = 0; i < 3; i++){ he[i][0] = vMin[i]; he[i][1] = vMax[i]; }
      else
        for (int i = 0; i < 3; i++){ he[i][0] = vMax[i]; he[i][1] = vMin[i]; }
      double m00 = 0, m01 = 0, m11 = 0;
      for (int i = 0; i < 3; i++){
        m00 += (double)he[i][0] * he[i][0];
        m01 += (double)he[i][0] * he[i][1];
        m11 += (double)he[i][1] * he[i][1];
      }
      double det = m00 * m11 - m01 * m01;
      double i00 = m11 / det, i01 = -m01 / det, i11 = m00 / det;
      for (int j = 0; j < 3; j++){
        g_A[j]     = (float)(i00 * he[j][0] + i01 * he[j][1]);
        g_A[3 + j] = (float)(i01 * he[j][0] + i11 * he[j][1]);
      }
      g_tick[1] = 0u;
    }
  }
}

// ---------------- pass 5: C coarse hists (additive LUT); tail = coarse resolve ----------------
__global__ void __launch_bounds__(256) k_Cq(int npix){
  __shared__ unsigned sh0[CBINS];
  __shared__ unsigned sh1[CBINS];
  __shared__ float cl0[256], cl1[256], cl2[256], cl3[256], cl4[256], cl5[256];
  BUILD_CLUT(cl0, cl1, cl2, cl3, cl4, cl5, g_A[0], g_A[1], g_A[2], g_A[3], g_A[4], g_A[5]);
  for (int b = threadIdx.x; b < CBINS; b += 256){ sh0[b] = 0u; sh1[b] = 0u; }
  __syncthreads();
  int n4 = npix >> 2;
  const uint4* PK = (const uint4*)g_pack;
  int stride = gridDim.x * blockDim.x;
  for (int i = blockIdx.x * blockDim.x + threadIdx.x; i < n4; i += stride){
    uint4 u = PK[i];
    unsigned pk[4] = {u.x, u.y, u.z, u.w};
    #pragma unroll
    for (int j = 0; j < 4; j++){
      unsigned b0 = pk[j] & 255u, b1 = (pk[j] >> 8) & 255u, b2 = (pk[j] >> 16) & 255u;
      int p0 = clamp22(cl0[b0] + cl1[b1] + cl2[b2]);
      int p1 = clamp22(cl3[b0] + cl4[b1] + cl5[b2]);
      atomicAdd(&sh0[p0 >> 10], 1u);
      atomicAdd(&sh1[p1 >> 10], 1u);
    }
  }
  __syncthreads();
  for (int b = threadIdx.x; b < CBINS; b += 256){
    unsigned v0 = sh0[b]; if (v0) atomicAdd(&g_hc[1][b], v0);
    unsigned v1 = sh1[b]; if (v1) atomicAdd(&g_hc[2][b], v1);
  }
  if (last_block(&g_tick[2], gridDim.x)){
    __shared__ unsigned rk[2];
    if (threadIdx.x == 0){
      float nm1 = (float)(npix - 1);
      float p = 0.99f * nm1;
      float l = floorf(p);
      rk[0] = (unsigned)l;
      rk[1] = (unsigned)ceilf(p);
      g_frac[2] = p - l;
    }
    __syncthreads();
    find_kth(g_hc[1], CBINS, rk, 2, &g_topbin[4], &g_rankin[4]);
    find_kth(g_hc[2], CBINS, rk, 2, &g_topbin[6], &g_rankin[6]);
    if (threadIdx.x == 0) g_tick[2] = 0u;
  }
}

// ---------------- pass 6: C fine hists (additive LUT); tail = maxC + G fuse ----------------
__global__ void __launch_bounds__(256) k_Cr(const float* __restrict__ HERef,
                                            const float* __restrict__ maxCRef, int npix){
  __shared__ unsigned fh[4][FBINS];
  __shared__ float cl0[256], cl1[256], cl2[256], cl3[256], cl4[256], cl5[256];
  BUILD_CLUT(cl0, cl1, cl2, cl3, cl4, cl5, g_A[0], g_A[1], g_A[2], g_A[3], g_A[4], g_A[5]);
  for (int b = threadIdx.x; b < 4 * FBINS; b += 256) ((unsigned*)fh)[b] = 0u;
  __syncthreads();
  int n4 = npix >> 2;
  const uint4* PK = (const uint4*)g_pack;
  int tb4 = (int)g_topbin[4], tb5 = (int)g_topbin[5], tb6 = (int)g_topbin[6], tb7 = (int)g_topbin[7];
  int stride = gridDim.x * blockDim.x;
  for (int i = blockIdx.x * blockDim.x + threadIdx.x; i < n4; i += stride){
    uint4 u = PK[i];
    unsigned pk[4] = {u.x, u.y, u.z, u.w};
    #pragma unroll
    for (int j = 0; j < 4; j++){
      unsigned b0 = pk[j] & 255u, b1 = (pk[j] >> 8) & 255u, b2 = (pk[j] >> 16) & 255u;
      int p0 = clamp22(cl0[b0] + cl1[b1] + cl2[b2]);
      int p1 = clamp22(cl3[b0] + cl4[b1] + cl5[b2]);
      int cb0 = p0 >> 10, fb0 = p0 & (FBINS - 1);
      int cb1 = p1 >> 10, fb1 = p1 & (FBINS - 1);
      if (cb0 == tb4) atomicAdd(&fh[0][fb0], 1u);
      if (cb0 == tb5) atomicAdd(&fh[1][fb0], 1u);
      if (cb1 == tb6) atomicAdd(&fh[2][fb1], 1u);
      if (cb1 == tb7) atomicAdd(&fh[3][fb1], 1u);
    }
  }
  __syncthreads();
  for (int b = threadIdx.x; b < 4 * FBINS; b += 256){
    unsigned v = ((unsigned*)fh)[b];
    if (v) atomicAdd(&((unsigned*)g_hf)[4 * FBINS + b], v);
  }
  if (last_block(&g_tick[3], gridDim.x)){
    __shared__ unsigned s_fb[4], s_rib[4];
    for (int q = 0; q < 4; q++)
      find_kth(g_hf[4 + q], FBINS, &g_rankin[4 + q], 1, &s_fb[q], &s_rib[q]);
    if (threadIdx.x == 0){
      float v[4];
      for (int q = 0; q < 4; q++)
        v[q] = C_LO + (((float)((g_topbin[4 + q] << 10) | s_fb[q])) + 0.5f) * (C_SPAN / TOT22);
      float fc = g_frac[2];
      float maxC0 = v[0] * (1.0f - fc) + v[1] * fc;
      float maxC1 = v[2] * (1.0f - fc) + v[3] * fc;
      float s0 = maxCRef[0] / maxC0;
      float s1 = maxCRef[1] / maxC1;
      for (int i = 0; i < 3; i++)
        for (int j = 0; j < 3; j++)
          g_G[i * 3 + j] = HERef[i * 2 + 0] * s0 * g_A[j] + HERef[i * 2 + 1] * s1 * g_A[3 + j];
      g_tick[3] = 0u;
    }
  }
}

// ---------------- pass 7: final output; tail = zero scratch ----------------
__global__ void __launch_bounds__(256) k_final(float* __restrict__ out, int npix){
  __shared__ float lut[256];
  BUILD_LUT(lut);
  int n4 = npix >> 2;
  const uint4* PK = (const uint4*)g_pack;
  float4* O = (float4*)out;
  float G00=g_G[0],G01=g_G[1],G02=g_G[2];
  float G10=g_G[3],G11=g_G[4],G12=g_G[5];
  float G20=g_G[6],G21=g_G[7],G22=g_G[8];
  int tid = blockIdx.x * blockDim.x + threadIdx.x;
  int stride = gridDim.x * blockDim.x;
  for (int i = tid; i < n4; i += stride){
    uint4 u = PK[i];
    unsigned pk[4] = {u.x, u.y, u.z, u.w};
    float res[12];
    #pragma unroll
    for (int j = 0; j < 4; j++){
      float o0 = lut[pk[j] & 255u], o1 = lut[(pk[j] >> 8) & 255u], o2 = lut[(pk[j] >> 16) & 255u];
      float y0 = o0*G00 + o1*G01 + o2*G02;
      float y1 = o0*G10 + o1*G11 + o2*G12;
      float y2 = o0*G20 + o1*G21 + o2*G22;
      res[3*j+0] = floorf(fminf(240.0f * __expf(-y0), 255.0f)) * (1.0f / 255.0f);
      res[3*j+1] = floorf(fminf(240.0f * __expf(-y1), 255.0f)) * (1.0f / 255.0f);
      res[3*j+2] = floorf(fminf(240.0f * __expf(-y2), 255.0f)) * (1.0f / 255.0f);
    }
    O[3*i+0] = make_float4(res[0], res[1], res[2],  res[3]);
    O[3*i+1] = make_float4(res[4], res[5], res[6],  res[7]);
    O[3*i+2] = make_float4(res[8], res[9], res[10], res[11]);
  }
  // zero scratch for next replay (tiny: ~80 KB)
  for (int i = tid; i < 3 * CBINS; i += stride) ((unsigned*)g_hc)[i] = 0u;
  for (int i = tid; i < 8 * FBINS; i += stride) ((unsigned*)g_hf)[i] = 0u;
  if (tid < 9) g_acc[tid] = 0.0;
  if (tid == 0) g_cnt = 0ull;
}

// ---------------- launch ----------------
extern "C" void kernel_launch(void* const* d_in, const int* in_sizes, int n_in,
                              void* d_out, int out_size) {
  const float* img     = (const float*)d_in[0];
  const float* HERef   = (const float*)d_in[1];
  const float* maxCRef = (const float*)d_in[2];
  float* out = (float*)d_out;
  int npix = in_sizes[0] / 3;

  k_stats <<<1024, 256>>>(img, npix);
  k_eig   <<<1, 32>>>();
  k_phiq  <<<1024, 256>>>(npix);
  k_phir  <<<1024, 256>>>(npix);
  k_Cq    <<<1024, 256>>>(npix);
  k_Cr    <<<1024, 256>>>(HERef, maxCRef, npix);
  k_final <<<2048, 256>>>(out, npix);
}